// round 15
// baseline (speedup 1.0000x reference)
#include <cuda_runtime.h>
#include <cuda_fp16.h>
#include <cstdint>

#define IN_DIM  1024
#define HID_DIM 4096
#define OUT_DIM 1024
#define N_EXP   8
#define BATCH   8192

// ---------------- scratch (device globals; no allocation) ----------------
__device__ int   g_counts[N_EXP];
__device__ int   g_offsets[N_EXP];
__device__ int   g_t1pref[N_EXP + 1];                  // 32*ceil(M_e/128) prefix (GEMM1 tiles)
__device__ int   g_expert_of[BATCH];
__device__ int   g_rank[BATCH];                        // rank of token within its expert
__device__ int   g_perm[BATCH];                        // gathered row -> original token
__device__ int   g_work;                               // fused work-queue counter
__device__ int   g_done[N_EXP];                        // completed GEMM1 tiles per expert
__device__ volatile int g_flag[N_EXP];                 // expert rows of g_hh ready
__device__ int   g_pzdone;                             // proj-convert + out-zero items done
__device__ __align__(16) __half g_xh[(size_t)BATCH * IN_DIM];            // x fp16, ORIGINAL order
__device__ __align__(16) __half g_hh[(size_t)BATCH * HID_DIM];           // hidden fp16, gathered order
__device__ __align__(16) __half g_ewh[(size_t)N_EXP * IN_DIM * HID_DIM]; // expert_w fp16 [e][k][n]
__device__ __align__(16) __half g_pwh[(size_t)HID_DIM * OUT_DIM];        // proj_w fp16 [k][n]

// ---------------- small kernels ----------------
__global__ void zero_kernel() {
    int t = threadIdx.x;
    if (t < N_EXP) { g_counts[t] = 0; g_done[t] = 0; g_flag[t] = 0; }
    if (t == 0)    { g_work = 0; g_pzdone = 0; }
}

// router: logits/argmax/one-hot, fp16 copy of x, and rank-within-expert
__global__ void router_kernel(const float* __restrict__ x,
                              const float* __restrict__ rw,
                              const float* __restrict__ rb,
                              float* __restrict__ route_out) {
    int warp = (blockIdx.x * blockDim.x + threadIdx.x) >> 5;
    int lane = threadIdx.x & 31;
    if (warp >= BATCH) return;
    const float2* xr = reinterpret_cast<const float2*>(x + (size_t)warp * IN_DIM);
    uint32_t* dst = reinterpret_cast<uint32_t*>(g_xh + (size_t)warp * IN_DIM);
    float acc[N_EXP];
#pragma unroll
    for (int e = 0; e < N_EXP; e++) acc[e] = 0.f;
#pragma unroll 4
    for (int i = 0; i < 16; i++) {
        int k2 = lane + 32 * i;                 // float2 index: floats 2*k2, 2*k2+1
        float2 v = xr[k2];
        const float4* w = reinterpret_cast<const float4*>(rw + (size_t)k2 * 2 * N_EXP);
        float4 w0 = w[0], w1 = w[1], w2 = w[2], w3 = w[3];
        acc[0] += v.x * w0.x + v.y * w2.x; acc[1] += v.x * w0.y + v.y * w2.y;
        acc[2] += v.x * w0.z + v.y * w2.z; acc[3] += v.x * w0.w + v.y * w2.w;
        acc[4] += v.x * w1.x + v.y * w3.x; acc[5] += v.x * w1.y + v.y * w3.y;
        acc[6] += v.x * w1.z + v.y * w3.z; acc[7] += v.x * w1.w + v.y * w3.w;
        __half2 h = __floats2half2_rn(v.x, v.y);
        dst[k2] = *reinterpret_cast<uint32_t*>(&h);
    }
#pragma unroll
    for (int e = 0; e < N_EXP; e++) {
#pragma unroll
        for (int off = 16; off > 0; off >>= 1)
            acc[e] += __shfl_down_sync(0xffffffffu, acc[e], off);
    }
    if (lane == 0) {
        float best = acc[0] + rb[0]; int bi = 0;
#pragma unroll
        for (int e = 1; e < N_EXP; e++) {
            float v = acc[e] + rb[e];
            if (v > best) { best = v; bi = e; }   // first-max wins == jnp.argmax
        }
        g_expert_of[warp] = bi;
        g_rank[warp] = atomicAdd(&g_counts[bi], 1);   // rank within expert
        float* ro = route_out + (size_t)warp * N_EXP;
#pragma unroll
        for (int e = 0; e < N_EXP; e++) ro[e] = (e == bi) ? 1.f : 0.f;
    }
}

// fused scan (redundant per block) + perm write + GEMM1 tile prefix
__global__ void perm_kernel() {
    __shared__ int offs[N_EXP];
    if (threadIdx.x == 0) {
        int s = 0, tp = 0;
#pragma unroll
        for (int e = 0; e < N_EXP; e++) {
            offs[e] = s;
            if (blockIdx.x == 0) {
                g_offsets[e] = s;
                g_t1pref[e] = tp;
                tp += 32 * ((g_counts[e] + 127) >> 7);
            }
            s += g_counts[e];
        }
        if (blockIdx.x == 0) g_t1pref[N_EXP] = tp;
    }
    __syncthreads();
    int i = blockIdx.x * blockDim.x + threadIdx.x;
    if (i < BATCH) {
        int e = g_expert_of[i];
        g_perm[offs[e] + g_rank[i]] = i;
    }
}

// fp32 -> fp16 conversion: expert_w part (side stream; joined before fused kernel)
__global__ void convert_expert_kernel(const float4* __restrict__ ew) {
    const size_t N4 = (size_t)N_EXP * IN_DIM * HID_DIM / 4;
    size_t stride = (size_t)gridDim.x * blockDim.x;
    uint2* dst = reinterpret_cast<uint2*>(g_ewh);
    for (size_t i = (size_t)blockIdx.x * blockDim.x + threadIdx.x; i < N4; i += stride) {
        float4 v = ew[i];
        __half2 h0 = __floats2half2_rn(v.x, v.y);
        __half2 h1 = __floats2half2_rn(v.z, v.w);
        uint2 u;
        u.x = *reinterpret_cast<uint32_t*>(&h0);
        u.y = *reinterpret_cast<uint32_t*>(&h1);
        dst[i] = u;
    }
}

// ---------------- fp16 mma.sync building blocks ----------------
constexpr int BM = 128, BN = 128, BK = 32, THREADS = 256, STAGES = 3;
constexpr int ASTRIDE = 80;                     // bytes/row: 32 halves + 8 pad
constexpr int BSTRIDE = 272;                    // bytes/row: 128 halves + 8 pad
constexpr int A_BYTES = BM * ASTRIDE;           // 10240
constexpr int B_BYTES = BK * BSTRIDE;           // 8704
constexpr int STAGE_BYTES = A_BYTES + B_BYTES;  // 18944
constexpr int PERM_OFF = STAGES * STAGE_BYTES;  // 56832
constexpr int META_OFF = PERM_OFF + BM * 4;     // 57344
constexpr int FUSED_SMEM = META_OFF + 128;      // 57472

// work queue layout
constexpr int N_PCONV = 256;                    // proj_w convert chunks (4096 float4 each)
constexpr int N_ZERO  = 128;                    // out zero chunks (16384 float4 each)
constexpr int N_UTIL  = N_PCONV + N_ZERO;       // 384
constexpr int N_T2    = (BATCH / BM) * (OUT_DIM / BN) * 4;  // 2048 (split-K=4)
constexpr int GRID_FUSED = 296;

__device__ __forceinline__ void cp_async16(uint32_t sm, const void* g, bool p) {
    int bytes = p ? 16 : 0;
    asm volatile("cp.async.cg.shared.global [%0], [%1], 16, %2;\n"
                 :: "r"(sm), "l"(g), "r"(bytes));
}
__device__ __forceinline__ void cp_commit() { asm volatile("cp.async.commit_group;\n"); }
template <int N> __device__ __forceinline__ void cp_wait() {
    asm volatile("cp.async.wait_group %0;\n" :: "n"(N));
}
__device__ __forceinline__ void ldsm_x4(uint32_t* r, uint32_t addr) {
    asm volatile("ldmatrix.sync.aligned.m8n8.x4.shared.b16 {%0,%1,%2,%3}, [%4];\n"
                 : "=r"(r[0]), "=r"(r[1]), "=r"(r[2]), "=r"(r[3]) : "r"(addr));
}
__device__ __forceinline__ void ldsm_x4_t(uint32_t* r, uint32_t addr) {
    asm volatile("ldmatrix.sync.aligned.m8n8.x4.trans.shared.b16 {%0,%1,%2,%3}, [%4];\n"
                 : "=r"(r[0]), "=r"(r[1]), "=r"(r[2]), "=r"(r[3]) : "r"(addr));
}
__device__ __forceinline__ void mma_f16(float* c, const uint32_t* a,
                                        uint32_t b0, uint32_t b1) {
    asm volatile(
        "mma.sync.aligned.m16n8k16.row.col.f32.f16.f16.f32 "
        "{%0,%1,%2,%3}, {%4,%5,%6,%7}, {%8,%9}, {%0,%1,%2,%3};\n"
        : "+f"(c[0]), "+f"(c[1]), "+f"(c[2]), "+f"(c[3])
        : "r"(a[0]), "r"(a[1]), "r"(a[2]), "r"(a[3]), "r"(b0), "r"(b1));
}

// ---------------- fused persistent kernel: utility + GEMM1 + GEMM2 ----------------
__global__ __launch_bounds__(THREADS, 2)
void moe_fused_kernel(const float4* __restrict__ pw,
                      const float* __restrict__ ebias,
                      const float* __restrict__ pbias,
                      float* __restrict__ outG) {
    extern __shared__ char smem[];
    uint32_t sm;
    asm("{ .reg .u64 t; cvta.to.shared.u64 t, %1; cvt.u32.u64 %0, t; }"
        : "=r"(sm) : "l"(smem));
    int* sperm    = reinterpret_cast<int*>(smem + PERM_OFF);
    int* s_tile   = reinterpret_cast<int*>(smem + META_OFF);
    int* s_counts = s_tile + 1;
    int* s_offs   = s_counts + N_EXP;
    int* s_pref   = s_offs + N_EXP;

    int tid = threadIdx.x;
    int lane = tid & 31, warp = tid >> 5;
    int wm = warp & 1, wn = warp >> 1;           // 2 warps (M=64) x 4 warps (N=32)
    uint32_t a_loff = (uint32_t)((lane & 15) * ASTRIDE + ((lane >> 4) & 1) * 16);
    uint32_t b_loff = (uint32_t)(((lane & 7) + ((lane >> 3) & 1) * 8) * BSTRIDE +
                                 ((lane >> 4) & 1) * 16);
    int g = lane >> 2, t4 = lane & 3;

    if (tid < N_EXP)     { s_counts[tid] = g_counts[tid]; s_offs[tid] = g_offsets[tid]; }
    if (tid < N_EXP + 1) s_pref[tid] = g_t1pref[tid];
    __syncthreads();
    const int W1 = s_pref[N_EXP];
    const int TOTAL = N_UTIL + W1 + N_T2;

    for (;;) {
        __syncthreads();
        if (tid == 0) *s_tile = atomicAdd(&g_work, 1);
        __syncthreads();
        int t = *s_tile;
        if (t >= TOTAL) break;

        // ---- utility items: proj_w convert / out zero ----
        if (t < N_UTIL) {
            if (t < N_PCONV) {
                const float4* src = pw + (size_t)t * 4096;
                uint2* dst = reinterpret_cast<uint2*>(g_pwh) + (size_t)t * 4096;
                for (int i = tid; i < 4096; i += THREADS) {
                    float4 v = src[i];
                    __half2 h0 = __floats2half2_rn(v.x, v.y);
                    __half2 h1 = __floats2half2_rn(v.z, v.w);
                    uint2 u;
                    u.x = *reinterpret_cast<uint32_t*>(&h0);
                    u.y = *reinterpret_cast<uint32_t*>(&h1);
                    dst[i] = u;
                }
            } else {
                float4* dst = reinterpret_cast<float4*>(outG) +
                              (size_t)(t - N_PCONV) * 16384;
                for (int i = tid; i < 16384; i += THREADS)
                    dst[i] = make_float4(0.f, 0.f, 0.f, 0.f);
            }
            __threadfence();
            __syncthreads();
            if (tid == 0) atomicAdd(&g_pzdone, 1);
            continue;
        }

        // ---- GEMM tile setup ----
        bool phase1 = t < N_UTIL + W1;
        int m_blk, n_blk, M, e = 0, kbase = 0;
        const __half *Abase, *Bbase;
        size_t strideA, strideB;
        const float* bias;
        if (phase1) {
            int t1 = t - N_UTIL;
#pragma unroll
            for (int q = 1; q < N_EXP; q++)
                if (t1 >= s_pref[q]) e = q;
            int local = t1 - s_pref[e];
            m_blk = (local >> 5) * BM;
            n_blk = (local & 31) * BN;
            M = s_counts[e];
            if (tid < BM) {
                int gi = s_offs[e] + m_blk + tid;
                sperm[tid] = g_perm[gi < BATCH ? gi : BATCH - 1];
            }
            Abase = g_xh;  strideA = IN_DIM;
            Bbase = g_ewh + (size_t)e * IN_DIM * HID_DIM;  strideB = HID_DIM;
            bias = ebias + (size_t)e * HID_DIM;
        } else {
            int t2 = t - N_UTIL - W1;
            int mi = t2 >> 5, rem = t2 & 31;
            m_blk = mi * BM;
            n_blk = (rem >> 2) * BN;
            kbase = (rem & 3) * 32;                 // k-tile base (split-K=4)
            M = BATCH;
            if (tid < BM) sperm[tid] = m_blk + tid;
            Abase = g_hh;  strideA = HID_DIM;
            Bbase = g_pwh; strideB = OUT_DIM;
            bias = pbias;
            if (tid == 0) {
                while (*(volatile int*)&g_pzdone < N_UTIL) __nanosleep(128);
#pragma unroll
                for (int q = 0; q < N_EXP; q++) {
                    int st = s_offs[q], en = st + s_counts[q];
                    if (st < m_blk + BM && en > m_blk)
                        while (g_flag[q] == 0) __nanosleep(128);
                }
                __threadfence();
            }
        }
        __syncthreads();   // sperm visible, producer data acquired

        auto load_tiles = [&](int kt, int s) {
            uint32_t sa = sm + s * STAGE_BYTES;
#pragma unroll
            for (int n = 0; n < 2; n++) {          // A: 128 rows x 4 chunks
                int id = tid + n * THREADS;
                int r = id >> 2, c = id & 3;
                bool ok = (m_blk + r) < M;
                const __half* src = Abase + (size_t)sperm[r] * strideA
                                    + (kbase + kt) * BK + c * 8;
                cp_async16(sa + r * ASTRIDE + c * 16, src, ok);
            }
            uint32_t sb = sa + A_BYTES;
#pragma unroll
            for (int n = 0; n < 2; n++) {          // B: 32 rows x 16 chunks
                int id = tid + n * THREADS;
                int r = id >> 4, c = id & 15;
                const __half* src = Bbase + (size_t)((kbase + kt) * BK + r) * strideB
                                    + n_blk + c * 8;
                cp_async16(sb + r * BSTRIDE + c * 16, src, true);
            }
            cp_commit();
        };

        float acc[4][4][4];
#pragma unroll
        for (int i = 0; i < 4; i++)
#pragma unroll
            for (int j = 0; j < 4; j++)
#pragma unroll
                for (int q = 0; q < 4; q++) acc[i][j][q] = 0.f;

        load_tiles(0, 0);
        load_tiles(1, 1);
#pragma unroll 1
        for (int kt = 0; kt < 32; kt++) {
            if (kt + 1 < 32) cp_wait<1>(); else cp_wait<0>();
            __syncthreads();
            if (kt + 2 < 32) load_tiles(kt + 2, (kt + 2) % STAGES);
            uint32_t sa = sm + (kt % STAGES) * STAGE_BYTES;
            uint32_t sb = sa + A_BYTES;
#pragma unroll
            for (int ks = 0; ks < 2; ks++) {
                uint32_t af[4][4], bf[2][4];
#pragma unroll
                for (int i = 0; i < 4; i++)
                    ldsm_x4(af[i], sa + a_loff + (wm * 64 + i * 16) * ASTRIDE + ks * 32);
#pragma unroll
                for (int j = 0; j < 2; j++)
                    ldsm_x4_t(bf[j], sb + b_loff + ks * 16 * BSTRIDE + (wn * 32 + j * 16) * 2);
#pragma unroll
                for (int i = 0; i < 4; i++) {
                    mma_f16(acc[i][0], af[i], bf[0][0], bf[0][1]);
                    mma_f16(acc[i][1], af[i], bf[0][2], bf[0][3]);
                    mma_f16(acc[i][2], af[i], bf[1][0], bf[1][1]);
                    mma_f16(acc[i][3], af[i], bf[1][2], bf[1][3]);
                }
            }
        }

        // ---- epilogue ----
        if (phase1) {
            __half* hC = g_hh + (size_t)s_offs[e] * HID_DIM;
#pragma unroll
            for (int i = 0; i < 4; i++) {
                int r0 = m_blk + wm * 64 + i * 16 + g;
                int r1 = r0 + 8;
#pragma unroll
                for (int j = 0; j < 4; j++) {
                    int c = n_blk + wn * 32 + j * 8 + 2 * t4;
                    float bv0 = bias[c], bv1 = bias[c + 1];
                    if (r0 < M) {
                        __half2 h = __floats2half2_rn(acc[i][j][0] + bv0, acc[i][j][1] + bv1);
                        *reinterpret_cast<uint32_t*>(hC + (size_t)r0 * HID_DIM + c) =
                            *reinterpret_cast<uint32_t*>(&h);
                    }
                    if (r1 < M) {
                        __half2 h = __floats2half2_rn(acc[i][j][2] + bv0, acc[i][j][3] + bv1);
                        *reinterpret_cast<uint32_t*>(hC + (size_t)r1 * HID_DIM + c) =
                            *reinterpret_cast<uint32_t*>(&h);
                    }
                }
            }
            __threadfence();
            __syncthreads();
            if (tid == 0) {
                int target = ((s_counts[e] + 127) >> 7) * 32;
                if (atomicAdd(&g_done[e], 1) == target - 1)
                    g_flag[e] = 1;                     // publish: expert rows ready
            }
        } else {
            bool addBias = (kbase == 0);
#pragma unroll
            for (int i = 0; i < 4; i++) {
                int r0 = m_blk + wm * 64 + i * 16 + g;
                int r1 = r0 + 8;
                int o0 = g_perm[r0], o1 = g_perm[r1];   // scatter rows back
                float* p0r = outG + (size_t)o0 * OUT_DIM;
                float* p1r = outG + (size_t)o1 * OUT_DIM;
#pragma unroll
                for (int j = 0; j < 4; j++) {
                    int c = n_blk + wn * 32 + j * 8 + 2 * t4;
                    float bv0 = addBias ? bias[c] : 0.f;
                    float bv1 = addBias ? bias[c + 1] : 0.f;
                    atomicAdd(p0r + c,     acc[i][j][0] + bv0);
                    atomicAdd(p0r + c + 1, acc[i][j][1] + bv1);
                    atomicAdd(p1r + c,     acc[i][j][2] + bv0);
                    atomicAdd(p1r + c + 1, acc[i][j][3] + bv1);
                }
            }
        }
    }
}

// ---------------- launch ----------------
extern "C" void kernel_launch(void* const* d_in, const int* in_sizes, int n_in,
                              void* d_out, int out_size) {
    const float* x        = (const float*)d_in[0];
    const float* router_w = (const float*)d_in[1];
    const float* router_b = (const float*)d_in[2];
    const float* expert_w = (const float*)d_in[3];
    const float* expert_b = (const float*)d_in[4];
    const float* proj_w   = (const float*)d_in[5];
    const float* proj_b   = (const float*)d_in[6];

    float* out       = (float*)d_out;
    float* route_out = out + (size_t)BATCH * OUT_DIM;   // [out | one_hot]

    // one-time setup on the FIRST (uncaptured correctness) call; reused during capture
    static cudaStream_t s2 = nullptr;
    static cudaEvent_t ev_fork = nullptr, ev_j1 = nullptr;
    if (!s2) {
        cudaStreamCreateWithFlags(&s2, cudaStreamNonBlocking);
        cudaEventCreateWithFlags(&ev_fork, cudaEventDisableTiming);
        cudaEventCreateWithFlags(&ev_j1, cudaEventDisableTiming);
        cudaFuncSetAttribute(moe_fused_kernel,
                             cudaFuncAttributeMaxDynamicSharedMemorySize, FUSED_SMEM);
    }

    // fork: expert weight conversion overlaps router/perm on the main stream
    cudaEventRecord(ev_fork, 0);
    cudaStreamWaitEvent(s2, ev_fork, 0);
    convert_expert_kernel<<<2048, 256, 0, s2>>>((const float4*)expert_w);
    cudaEventRecord(ev_j1, s2);                      // expert weights ready

    zero_kernel<<<1, 32>>>();
    router_kernel<<<BATCH / 8, 256>>>(x, router_w, router_b, route_out);
    perm_kernel<<<BATCH / 256, 256>>>();

    cudaStreamWaitEvent(0, ev_j1, 0);
    moe_fused_kernel<<<GRID_FUSED, THREADS, FUSED_SMEM>>>(
        (const float4*)proj_w, expert_b, proj_b, out);
}

// round 16
// speedup vs baseline: 1.0640x; 1.0640x over previous
#include <cuda_runtime.h>
#include <cuda_fp16.h>
#include <cstdint>

#define IN_DIM  1024
#define HID_DIM 4096
#define OUT_DIM 1024
#define N_EXP   8
#define BATCH   8192

// ---------------- scratch (device globals; no allocation) ----------------
__device__ int   g_counts[N_EXP];                      // router atomics (re-zeroed by perm)
__device__ int   g_counts2[N_EXP];                     // stable copy for GEMM1
__device__ int   g_offsets[N_EXP];
__device__ int   g_t1pref[N_EXP + 1];                  // GEMM1 tile prefix per expert
__device__ int   g_expert_of[BATCH];
__device__ int   g_rank[BATCH];                        // rank of token within its expert
__device__ int   g_perm[BATCH];                        // gathered row -> original token
__device__ __align__(16) __half g_xh[(size_t)BATCH * IN_DIM];            // x fp16, ORIGINAL order
__device__ __align__(16) __half g_hh[(size_t)BATCH * HID_DIM];           // hidden fp16, gathered order
__device__ __align__(16) __half g_ewh[(size_t)N_EXP * IN_DIM * HID_DIM]; // expert_w fp16 [e][k][n]
__device__ __align__(16) __half g_pwh[(size_t)HID_DIM * OUT_DIM];        // proj_w fp16 [k][n]

// ---------------- small kernels ----------------
// zero the out region of d_out (split-K accumulates into it with atomics)
__global__ void zero_out_kernel(float4* __restrict__ out4) {
    const size_t N4 = (size_t)BATCH * OUT_DIM / 4;
    size_t stride = (size_t)gridDim.x * blockDim.x;
    for (size_t i = (size_t)blockIdx.x * blockDim.x + threadIdx.x; i < N4; i += stride)
        out4[i] = make_float4(0.f, 0.f, 0.f, 0.f);
}

// router: logits/argmax/one-hot, fp16 copy of x, and rank-within-expert
__global__ void router_kernel(const float* __restrict__ x,
                              const float* __restrict__ rw,
                              const float* __restrict__ rb,
                              float* __restrict__ route_out) {
    int warp = (blockIdx.x * blockDim.x + threadIdx.x) >> 5;
    int lane = threadIdx.x & 31;
    if (warp >= BATCH) return;
    const float2* xr = reinterpret_cast<const float2*>(x + (size_t)warp * IN_DIM);
    uint32_t* dst = reinterpret_cast<uint32_t*>(g_xh + (size_t)warp * IN_DIM);
    float acc[N_EXP];
#pragma unroll
    for (int e = 0; e < N_EXP; e++) acc[e] = 0.f;
#pragma unroll 4
    for (int i = 0; i < 16; i++) {
        int k2 = lane + 32 * i;                 // float2 index: floats 2*k2, 2*k2+1
        float2 v = xr[k2];
        const float4* w = reinterpret_cast<const float4*>(rw + (size_t)k2 * 2 * N_EXP);
        float4 w0 = w[0], w1 = w[1], w2 = w[2], w3 = w[3];
        acc[0] += v.x * w0.x + v.y * w2.x; acc[1] += v.x * w0.y + v.y * w2.y;
        acc[2] += v.x * w0.z + v.y * w2.z; acc[3] += v.x * w0.w + v.y * w2.w;
        acc[4] += v.x * w1.x + v.y * w3.x; acc[5] += v.x * w1.y + v.y * w3.y;
        acc[6] += v.x * w1.z + v.y * w3.z; acc[7] += v.x * w1.w + v.y * w3.w;
        __half2 h = __floats2half2_rn(v.x, v.y);
        dst[k2] = *reinterpret_cast<uint32_t*>(&h);
    }
#pragma unroll
    for (int e = 0; e < N_EXP; e++) {
#pragma unroll
        for (int off = 16; off > 0; off >>= 1)
            acc[e] += __shfl_down_sync(0xffffffffu, acc[e], off);
    }
    if (lane == 0) {
        float best = acc[0] + rb[0]; int bi = 0;
#pragma unroll
        for (int e = 1; e < N_EXP; e++) {
            float v = acc[e] + rb[e];
            if (v > best) { best = v; bi = e; }   // first-max wins == jnp.argmax
        }
        g_expert_of[warp] = bi;
        g_rank[warp] = atomicAdd(&g_counts[bi], 1);   // rank within expert
        float* ro = route_out + (size_t)warp * N_EXP;
#pragma unroll
        for (int e = 0; e < N_EXP; e++) ro[e] = (e == bi) ? 1.f : 0.f;
    }
}

// fused scan + perm write + GEMM1 tile prefix; block 0 also snapshots counts
// into g_counts2 and re-zeroes g_counts for the next graph replay.
__global__ void perm_kernel() {
    __shared__ int offs[N_EXP];
    if (threadIdx.x == 0) {
        int s = 0, tp = 0;
#pragma unroll
        for (int e = 0; e < N_EXP; e++) {
            int cnt = g_counts[e];
            offs[e] = s;
            if (blockIdx.x == 0) {
                g_offsets[e] = s;
                g_counts2[e] = cnt;
                g_t1pref[e] = tp;
                tp += 32 * ((cnt + 127) >> 7);
            }
            s += cnt;
        }
        if (blockIdx.x == 0) g_t1pref[N_EXP] = tp;
    }
    __syncthreads();
    int i = blockIdx.x * blockDim.x + threadIdx.x;
    if (i < BATCH) {
        int e = g_expert_of[i];
        g_perm[offs[e] + g_rank[i]] = i;
    }
    // after all blocks' reads of g_counts are done? Block 0 thread 0 already
    // snapshotted; other blocks only read via their own offs scan above.
    // Re-zero from block 0 AFTER its own scan; other blocks' scans read
    // g_counts concurrently -> must not zero until they're done. Use last-block
    // trick instead: each block signals; the last one zeroes.
    __shared__ int lastflag;
    __threadfence();
    if (threadIdx.x == 0) {
        __device__ static int done_blocks;   // zero-initialized once at module load
        int prev = atomicAdd(&done_blocks, 1);
        lastflag = (prev == gridDim.x - 1) ? 1 : 0;
        if (lastflag) done_blocks = 0;
    }
    __syncthreads();
    if (lastflag && threadIdx.x < N_EXP) g_counts[threadIdx.x] = 0;
}

// fp32 -> fp16 conversion: expert_w part (joined before GEMM1)
__global__ void convert_expert_kernel(const float4* __restrict__ ew) {
    const size_t N4 = (size_t)N_EXP * IN_DIM * HID_DIM / 4;
    size_t stride = (size_t)gridDim.x * blockDim.x;
    uint2* dst = reinterpret_cast<uint2*>(g_ewh);
    for (size_t i = (size_t)blockIdx.x * blockDim.x + threadIdx.x; i < N4; i += stride) {
        float4 v = ew[i];
        __half2 h0 = __floats2half2_rn(v.x, v.y);
        __half2 h1 = __floats2half2_rn(v.z, v.w);
        uint2 u;
        u.x = *reinterpret_cast<uint32_t*>(&h0);
        u.y = *reinterpret_cast<uint32_t*>(&h1);
        dst[i] = u;
    }
}

// fp32 -> fp16 conversion: proj_w part (joined before GEMM2)
__global__ void convert_proj_kernel(const float4* __restrict__ pw) {
    const size_t N4 = (size_t)HID_DIM * OUT_DIM / 4;
    size_t stride = (size_t)gridDim.x * blockDim.x;
    uint2* dst = reinterpret_cast<uint2*>(g_pwh);
    for (size_t i = (size_t)blockIdx.x * blockDim.x + threadIdx.x; i < N4; i += stride) {
        float4 v = pw[i];
        __half2 h0 = __floats2half2_rn(v.x, v.y);
        __half2 h1 = __floats2half2_rn(v.z, v.w);
        uint2 u;
        u.x = *reinterpret_cast<uint32_t*>(&h0);
        u.y = *reinterpret_cast<uint32_t*>(&h1);
        dst[i] = u;
    }
}

// ---------------- fp16 mma.sync GEMM building blocks ----------------
constexpr int BM = 128, BN = 128, BK = 32, THREADS = 256, STAGES = 3;
constexpr int ASTRIDE = 80;                     // bytes/row: 32 halves + 8 pad
constexpr int BSTRIDE = 272;                    // bytes/row: 128 halves + 8 pad
constexpr int A_BYTES = BM * ASTRIDE;           // 10240
constexpr int B_BYTES = BK * BSTRIDE;           // 8704
constexpr int STAGE_BYTES = A_BYTES + B_BYTES;  // 18944
constexpr int PERM_OFF = STAGES * STAGE_BYTES;  // 56832
constexpr int GEMM_SMEM = PERM_OFF + BM * 4;    // 57344 (gemm1: +perm slice)
constexpr int GEMM2_SMEM = STAGES * STAGE_BYTES; // 56832
constexpr int MAX_T1 = 2304;                    // 72 m-tiles * 32 n-tiles upper bound

__device__ __forceinline__ void cp_async16(uint32_t sm, const void* g, bool p) {
    int bytes = p ? 16 : 0;
    asm volatile("cp.async.cg.shared.global [%0], [%1], 16, %2;\n"
                 :: "r"(sm), "l"(g), "r"(bytes));
}
__device__ __forceinline__ void cp_commit() { asm volatile("cp.async.commit_group;\n"); }
template <int N> __device__ __forceinline__ void cp_wait() {
    asm volatile("cp.async.wait_group %0;\n" :: "n"(N));
}
__device__ __forceinline__ void ldsm_x4(uint32_t* r, uint32_t addr) {
    asm volatile("ldmatrix.sync.aligned.m8n8.x4.shared.b16 {%0,%1,%2,%3}, [%4];\n"
                 : "=r"(r[0]), "=r"(r[1]), "=r"(r[2]), "=r"(r[3]) : "r"(addr));
}
__device__ __forceinline__ void ldsm_x4_t(uint32_t* r, uint32_t addr) {
    asm volatile("ldmatrix.sync.aligned.m8n8.x4.trans.shared.b16 {%0,%1,%2,%3}, [%4];\n"
                 : "=r"(r[0]), "=r"(r[1]), "=r"(r[2]), "=r"(r[3]) : "r"(addr));
}
__device__ __forceinline__ void mma_f16(float* c, const uint32_t* a,
                                        uint32_t b0, uint32_t b1) {
    asm volatile(
        "mma.sync.aligned.m16n8k16.row.col.f32.f16.f16.f32 "
        "{%0,%1,%2,%3}, {%4,%5,%6,%7}, {%8,%9}, {%0,%1,%2,%3};\n"
        : "+f"(c[0]), "+f"(c[1]), "+f"(c[2]), "+f"(c[3])
        : "r"(a[0]), "r"(a[1]), "r"(a[2]), "r"(a[3]), "r"(b0), "r"(b1));
}

// ---------------- GEMM1: expert GEMM, compact 1-D grid over real tiles ----------------
__global__ __launch_bounds__(THREADS, 2)
void gemm1_kernel(const float* __restrict__ biasGlob) {
    constexpr int KT = IN_DIM / BK;     // 32

    int t = blockIdx.x;
    if (t >= g_t1pref[N_EXP]) return;   // beyond real tile count
    int e = 0;
#pragma unroll
    for (int q = 1; q < N_EXP; q++)
        if (t >= g_t1pref[q]) e = q;
    int local = t - g_t1pref[e];
    int m_blk = (local >> 5) * BM;
    int n_blk = (local & 31) * BN;
    int M = g_counts2[e];

    extern __shared__ char smem[];
    uint32_t sm;
    asm("{ .reg .u64 t; cvta.to.shared.u64 t, %1; cvt.u32.u64 %0, t; }"
        : "=r"(sm) : "l"(smem));
    int* sperm = reinterpret_cast<int*>(smem + PERM_OFF);
    int tid = threadIdx.x;
    int lane = tid & 31, warp = tid >> 5;
    int wm = warp & 1, wn = warp >> 1;           // 2 warps (M=64) x 4 warps (N=32)
    uint32_t a_loff = (uint32_t)((lane & 15) * ASTRIDE + ((lane >> 4) & 1) * 16);
    uint32_t b_loff = (uint32_t)(((lane & 7) + ((lane >> 3) & 1) * 8) * BSTRIDE +
                                 ((lane >> 4) & 1) * 16);
    int g = lane >> 2, t4 = lane & 3;

    const __half* B = g_ewh + (size_t)e * IN_DIM * HID_DIM;
    const float* bias = biasGlob + (size_t)e * HID_DIM;
    __half* hC = g_hh + (size_t)g_offsets[e] * HID_DIM;

    if (tid < BM) {
        int gi = g_offsets[e] + m_blk + tid;
        sperm[tid] = g_perm[gi < BATCH ? gi : BATCH - 1];
    }
    __syncthreads();

    auto load_tiles = [&](int kt, int s) {
        uint32_t sa = sm + s * STAGE_BYTES;
#pragma unroll
        for (int n = 0; n < 2; n++) {          // A: 128 rows x 4 chunks
            int id = tid + n * THREADS;
            int r = id >> 2, c = id & 3;
            bool ok = (m_blk + r) < M;
            const __half* src = g_xh + (size_t)sperm[r] * IN_DIM + kt * BK + c * 8;
            cp_async16(sa + r * ASTRIDE + c * 16, src, ok);
        }
        uint32_t sb = sa + A_BYTES;
#pragma unroll
        for (int n = 0; n < 2; n++) {          // B: 32 rows x 16 chunks
            int id = tid + n * THREADS;
            int r = id >> 4, c = id & 15;
            const __half* src = B + (size_t)(kt * BK + r) * HID_DIM + n_blk + c * 8;
            cp_async16(sb + r * BSTRIDE + c * 16, src, true);
        }
        cp_commit();
    };

    float acc[4][4][4];
#pragma unroll
    for (int i = 0; i < 4; i++)
#pragma unroll
        for (int j = 0; j < 4; j++)
#pragma unroll
            for (int q = 0; q < 4; q++) acc[i][j][q] = 0.f;

    load_tiles(0, 0);
    load_tiles(1, 1);
    for (int kt = 0; kt < KT; kt++) {
        if (kt + 1 < KT) cp_wait<1>(); else cp_wait<0>();
        __syncthreads();
        if (kt + 2 < KT) load_tiles(kt + 2, (kt + 2) % STAGES);
        uint32_t sa = sm + (kt % STAGES) * STAGE_BYTES;
        uint32_t sb = sa + A_BYTES;
#pragma unroll
        for (int ks = 0; ks < 2; ks++) {
            uint32_t af[4][4], bf[2][4];
#pragma unroll
            for (int i = 0; i < 4; i++)
                ldsm_x4(af[i], sa + a_loff + (wm * 64 + i * 16) * ASTRIDE + ks * 32);
#pragma unroll
            for (int j = 0; j < 2; j++)
                ldsm_x4_t(bf[j], sb + b_loff + ks * 16 * BSTRIDE + (wn * 32 + j * 16) * 2);
#pragma unroll
            for (int i = 0; i < 4; i++) {
                mma_f16(acc[i][0], af[i], bf[0][0], bf[0][1]);
                mma_f16(acc[i][1], af[i], bf[0][2], bf[0][3]);
                mma_f16(acc[i][2], af[i], bf[1][0], bf[1][1]);
                mma_f16(acc[i][3], af[i], bf[1][2], bf[1][3]);
            }
        }
    }

    // epilogue -> g_hh (fp16)
#pragma unroll
    for (int i = 0; i < 4; i++) {
        int r0 = m_blk + wm * 64 + i * 16 + g;
        int r1 = r0 + 8;
#pragma unroll
        for (int j = 0; j < 4; j++) {
            int c = n_blk + wn * 32 + j * 8 + 2 * t4;
            float bv0 = bias[c], bv1 = bias[c + 1];
            if (r0 < M) {
                __half2 h = __floats2half2_rn(acc[i][j][0] + bv0, acc[i][j][1] + bv1);
                *reinterpret_cast<uint32_t*>(hC + (size_t)r0 * HID_DIM + c) =
                    *reinterpret_cast<uint32_t*>(&h);
            }
            if (r1 < M) {
                __half2 h = __floats2half2_rn(acc[i][j][2] + bv0, acc[i][j][3] + bv1);
                *reinterpret_cast<uint32_t*>(hC + (size_t)r1 * HID_DIM + c) =
                    *reinterpret_cast<uint32_t*>(&h);
            }
        }
    }
}

// ---------------- GEMM2: proj GEMM with split-K=4 ----------------
constexpr int KSPLIT = 4;
constexpr int KT2 = (HID_DIM / BK) / KSPLIT;   // 32 k-tiles per slice

__global__ __launch_bounds__(THREADS, 2)
void gemm2_kernel(const float* __restrict__ bias,
                  float* __restrict__ outGlob) {
    extern __shared__ char smem[];
    uint32_t sm;
    asm("{ .reg .u64 t; cvta.to.shared.u64 t, %1; cvt.u32.u64 %0, t; }"
        : "=r"(sm) : "l"(smem));
    int tid = threadIdx.x;
    int lane = tid & 31, warp = tid >> 5;
    int wm = warp & 1, wn = warp >> 1;           // 2 warps (M=64) x 4 warps (N=32)
    uint32_t a_loff = (uint32_t)((lane & 15) * ASTRIDE + ((lane >> 4) & 1) * 16);
    uint32_t b_loff = (uint32_t)(((lane & 7) + ((lane >> 3) & 1) * 8) * BSTRIDE +
                                 ((lane >> 4) & 1) * 16);
    int g = lane >> 2, t4 = lane & 3;

    int m_blk = blockIdx.y * BM;
    int n_blk = blockIdx.x * BN;
    int k0 = blockIdx.z * KT2;                   // k-tile base of this slice

    auto load_tiles = [&](int kt, int s) {
        uint32_t sa = sm + s * STAGE_BYTES;
#pragma unroll
        for (int n = 0; n < 2; n++) {          // A: 128 rows x 4 chunks
            int id = tid + n * THREADS;
            int r = id >> 2, c = id & 3;
            const __half* src = g_hh + (size_t)(m_blk + r) * HID_DIM
                                + (k0 + kt) * BK + c * 8;
            cp_async16(sa + r * ASTRIDE + c * 16, src, true);
        }
        uint32_t sb = sa + A_BYTES;
#pragma unroll
        for (int n = 0; n < 2; n++) {          // B: 32 rows x 16 chunks
            int id = tid + n * THREADS;
            int r = id >> 4, c = id & 15;
            const __half* src = g_pwh + (size_t)((k0 + kt) * BK + r) * OUT_DIM
                                + n_blk + c * 8;
            cp_async16(sb + r * BSTRIDE + c * 16, src, true);
        }
        cp_commit();
    };

    float acc[4][4][4];
#pragma unroll
    for (int i = 0; i < 4; i++)
#pragma unroll
        for (int j = 0; j < 4; j++)
#pragma unroll
            for (int q = 0; q < 4; q++) acc[i][j][q] = 0.f;

    load_tiles(0, 0);
    load_tiles(1, 1);
    for (int kt = 0; kt < KT2; kt++) {
        if (kt + 1 < KT2) cp_wait<1>(); else cp_wait<0>();
        __syncthreads();
        if (kt + 2 < KT2) load_tiles(kt + 2, (kt + 2) % STAGES);
        uint32_t sa = sm + (kt % STAGES) * STAGE_BYTES;
        uint32_t sb = sa + A_BYTES;
#pragma unroll
        for (int ks = 0; ks < 2; ks++) {
            uint32_t af[4][4], bf[2][4];
#pragma unroll
            for (int i = 0; i < 4; i++)
                ldsm_x4(af[i], sa + a_loff + (wm * 64 + i * 16) * ASTRIDE + ks * 32);
#pragma unroll
            for (int j = 0; j < 2; j++)
                ldsm_x4_t(bf[j], sb + b_loff + ks * 16 * BSTRIDE + (wn * 32 + j * 16) * 2);
#pragma unroll
            for (int i = 0; i < 4; i++) {
                mma_f16(acc[i][0], af[i], bf[0][0], bf[0][1]);
                mma_f16(acc[i][1], af[i], bf[0][2], bf[0][3]);
                mma_f16(acc[i][2], af[i], bf[1][0], bf[1][1]);
                mma_f16(acc[i][3], af[i], bf[1][2], bf[1][3]);
            }
        }
    }

    // epilogue: accumulate partial into d_out (scattered rows), bias on slice 0
    bool addBias = (blockIdx.z == 0);
#pragma unroll
    for (int i = 0; i < 4; i++) {
        int r0 = m_blk + wm * 64 + i * 16 + g;
        int r1 = r0 + 8;
        int o0 = g_perm[r0], o1 = g_perm[r1];
        float* p0r = outGlob + (size_t)o0 * OUT_DIM;
        float* p1r = outGlob + (size_t)o1 * OUT_DIM;
#pragma unroll
        for (int j = 0; j < 4; j++) {
            int c = n_blk + wn * 32 + j * 8 + 2 * t4;
            float bv0 = addBias ? bias[c] : 0.f;
            float bv1 = addBias ? bias[c + 1] : 0.f;
            atomicAdd(p0r + c,     acc[i][j][0] + bv0);
            atomicAdd(p0r + c + 1, acc[i][j][1] + bv1);
            atomicAdd(p1r + c,     acc[i][j][2] + bv0);
            atomicAdd(p1r + c + 1, acc[i][j][3] + bv1);
        }
    }
}

// ---------------- launch ----------------
extern "C" void kernel_launch(void* const* d_in, const int* in_sizes, int n_in,
                              void* d_out, int out_size) {
    const float* x        = (const float*)d_in[0];
    const float* router_w = (const float*)d_in[1];
    const float* router_b = (const float*)d_in[2];
    const float* expert_w = (const float*)d_in[3];
    const float* expert_b = (const float*)d_in[4];
    const float* proj_w   = (const float*)d_in[5];
    const float* proj_b   = (const float*)d_in[6];

    float* out       = (float*)d_out;
    float* route_out = out + (size_t)BATCH * OUT_DIM;   // [out | one_hot]

    // one-time setup on the FIRST (uncaptured correctness) call; reused during capture
    static cudaStream_t s2 = nullptr;
    static cudaEvent_t ev_fork = nullptr, ev_j1 = nullptr, ev_j2 = nullptr;
    if (!s2) {
        cudaStreamCreateWithFlags(&s2, cudaStreamNonBlocking);
        cudaEventCreateWithFlags(&ev_fork, cudaEventDisableTiming);
        cudaEventCreateWithFlags(&ev_j1, cudaEventDisableTiming);
        cudaEventCreateWithFlags(&ev_j2, cudaEventDisableTiming);
        cudaFuncSetAttribute(gemm1_kernel,
                             cudaFuncAttributeMaxDynamicSharedMemorySize, GEMM_SMEM);
        cudaFuncSetAttribute(gemm2_kernel,
                             cudaFuncAttributeMaxDynamicSharedMemorySize, GEMM2_SMEM);
    }

    // fork: side stream does weight conversion + out zeroing, overlapping
    // with router/perm on the main stream.
    cudaEventRecord(ev_fork, 0);
    cudaStreamWaitEvent(s2, ev_fork, 0);
    convert_expert_kernel<<<2048, 256, 0, s2>>>((const float4*)expert_w);
    cudaEventRecord(ev_j1, s2);                      // expert weights ready
    convert_proj_kernel<<<256, 256, 0, s2>>>((const float4*)proj_w);
    zero_out_kernel<<<512, 256, 0, s2>>>((float4*)out);
    cudaEventRecord(ev_j2, s2);                      // proj weights + zeroed out ready

    router_kernel<<<BATCH / 8, 256>>>(x, router_w, router_b, route_out);
    perm_kernel<<<BATCH / 256, 256>>>();

    cudaStreamWaitEvent(0, ev_j1, 0);
    gemm1_kernel<<<MAX_T1, THREADS, GEMM_SMEM>>>(expert_b);

    cudaStreamWaitEvent(0, ev_j2, 0);
    gemm2_kernel<<<dim3(OUT_DIM / BN, BATCH / BM, KSPLIT),
                   THREADS, GEMM2_SMEM>>>(proj_b, out);
}

// round 17
// speedup vs baseline: 1.0730x; 1.0085x over previous
#include <cuda_runtime.h>
#include <cuda_fp16.h>
#include <cstdint>

#define IN_DIM  1024
#define HID_DIM 4096
#define OUT_DIM 1024
#define N_EXP   8
#define BATCH   8192

// ---------------- scratch (device globals; no allocation) ----------------
__device__ int   g_counts[N_EXP];                      // router atomics (re-zeroed by perm)
__device__ int   g_counts2[N_EXP];                     // stable copy for GEMM1
__device__ int   g_offsets[N_EXP];
__device__ int   g_t1pref[N_EXP + 1];                  // GEMM1 tile prefix per expert
__device__ int   g_expert_of[BATCH];
__device__ int   g_rank[BATCH];                        // rank of token within its expert
__device__ int   g_perm[BATCH];                        // gathered row -> original token
__device__ __align__(16) __half g_xh[(size_t)BATCH * IN_DIM];            // x fp16, ORIGINAL order
__device__ __align__(16) __half g_hh[(size_t)BATCH * HID_DIM];           // hidden fp16, gathered order
__device__ __align__(16) __half g_ewh[(size_t)N_EXP * IN_DIM * HID_DIM]; // expert_w fp16 [e][k][n]
__device__ __align__(16) __half g_pwh[(size_t)HID_DIM * OUT_DIM];        // proj_w fp16 [k][n]

// ---------------- small kernels ----------------
// zero the out region of d_out (split-K accumulates into it with atomics)
__global__ void zero_out_kernel(float4* __restrict__ out4) {
    const size_t N4 = (size_t)BATCH * OUT_DIM / 4;
    size_t stride = (size_t)gridDim.x * blockDim.x;
    for (size_t i = (size_t)blockIdx.x * blockDim.x + threadIdx.x; i < N4; i += stride)
        out4[i] = make_float4(0.f, 0.f, 0.f, 0.f);
}

// router: 8 tokens per warp. Each lane loads rw[k2] (64B) ONCE and applies it
// to 8 tokens -> 8x less router_w L1 traffic than 1 token/warp (was L1-bound
// at 43us with 256MB of redundant weight reads). Also emits fp16 x copy.
constexpr int TPW = 8;                         // tokens per warp
__global__ void router_kernel(const float* __restrict__ x,
                              const float* __restrict__ rw,
                              const float* __restrict__ rb,
                              float* __restrict__ route_out) {
    int warp = (blockIdx.x * blockDim.x + threadIdx.x) >> 5;
    int lane = threadIdx.x & 31;
    int tok0 = warp * TPW;
    if (tok0 >= BATCH) return;
    const float2* xr = reinterpret_cast<const float2*>(x) + (size_t)tok0 * (IN_DIM / 2);
    uint32_t* dst = reinterpret_cast<uint32_t*>(g_xh) + (size_t)tok0 * (IN_DIM / 2);

    float acc[TPW][N_EXP];
#pragma unroll
    for (int t = 0; t < TPW; t++)
#pragma unroll
        for (int e = 0; e < N_EXP; e++) acc[t][e] = 0.f;

    for (int i = 0; i < 16; i++) {
        int k2 = lane + 32 * i;                 // float2 index: floats 2*k2, 2*k2+1
        const float4* w = reinterpret_cast<const float4*>(rw + (size_t)k2 * 2 * N_EXP);
        float4 w0 = w[0], w1 = w[1], w2 = w[2], w3 = w[3];
#pragma unroll
        for (int t = 0; t < TPW; t++) {
            float2 v = xr[(size_t)t * (IN_DIM / 2) + k2];
            acc[t][0] += v.x * w0.x + v.y * w2.x;
            acc[t][1] += v.x * w0.y + v.y * w2.y;
            acc[t][2] += v.x * w0.z + v.y * w2.z;
            acc[t][3] += v.x * w0.w + v.y * w2.w;
            acc[t][4] += v.x * w1.x + v.y * w3.x;
            acc[t][5] += v.x * w1.y + v.y * w3.y;
            acc[t][6] += v.x * w1.z + v.y * w3.z;
            acc[t][7] += v.x * w1.w + v.y * w3.w;
            __half2 h = __floats2half2_rn(v.x, v.y);
            dst[(size_t)t * (IN_DIM / 2) + k2] = *reinterpret_cast<uint32_t*>(&h);
        }
    }
#pragma unroll
    for (int t = 0; t < TPW; t++)
#pragma unroll
        for (int e = 0; e < N_EXP; e++) {
#pragma unroll
            for (int off = 16; off > 0; off >>= 1)
                acc[t][e] += __shfl_down_sync(0xffffffffu, acc[t][e], off);
        }
    if (lane == 0) {
#pragma unroll
        for (int t = 0; t < TPW; t++) {
            int token = tok0 + t;
            float best = acc[t][0] + rb[0]; int bi = 0;
#pragma unroll
            for (int e = 1; e < N_EXP; e++) {
                float v = acc[t][e] + rb[e];
                if (v > best) { best = v; bi = e; }   // first-max wins == jnp.argmax
            }
            g_expert_of[token] = bi;
            g_rank[token] = atomicAdd(&g_counts[bi], 1);   // rank within expert
            float* ro = route_out + (size_t)token * N_EXP;
#pragma unroll
            for (int e = 0; e < N_EXP; e++) ro[e] = (e == bi) ? 1.f : 0.f;
        }
    }
}

// fused scan + perm write + GEMM1 tile prefix; last finishing block re-zeroes
// g_counts for the next graph replay (counts snapshotted into g_counts2).
__global__ void perm_kernel() {
    __shared__ int offs[N_EXP];
    if (threadIdx.x == 0) {
        int s = 0, tp = 0;
#pragma unroll
        for (int e = 0; e < N_EXP; e++) {
            int cnt = g_counts[e];
            offs[e] = s;
            if (blockIdx.x == 0) {
                g_offsets[e] = s;
                g_counts2[e] = cnt;
                g_t1pref[e] = tp;
                tp += 32 * ((cnt + 127) >> 7);
            }
            s += cnt;
        }
        if (blockIdx.x == 0) g_t1pref[N_EXP] = tp;
    }
    __syncthreads();
    int i = blockIdx.x * blockDim.x + threadIdx.x;
    if (i < BATCH) {
        int e = g_expert_of[i];
        g_perm[offs[e] + g_rank[i]] = i;
    }
    __shared__ int lastflag;
    __threadfence();
    if (threadIdx.x == 0) {
        __device__ static int done_blocks;   // zero-initialized at module load
        int prev = atomicAdd(&done_blocks, 1);
        lastflag = (prev == gridDim.x - 1) ? 1 : 0;
        if (lastflag) done_blocks = 0;
    }
    __syncthreads();
    if (lastflag && threadIdx.x < N_EXP) g_counts[threadIdx.x] = 0;
}

// fp32 -> fp16 conversion: expert_w part (joined before GEMM1)
__global__ void convert_expert_kernel(const float4* __restrict__ ew) {
    const size_t N4 = (size_t)N_EXP * IN_DIM * HID_DIM / 4;
    size_t stride = (size_t)gridDim.x * blockDim.x;
    uint2* dst = reinterpret_cast<uint2*>(g_ewh);
    for (size_t i = (size_t)blockIdx.x * blockDim.x + threadIdx.x; i < N4; i += stride) {
        float4 v = ew[i];
        __half2 h0 = __floats2half2_rn(v.x, v.y);
        __half2 h1 = __floats2half2_rn(v.z, v.w);
        uint2 u;
        u.x = *reinterpret_cast<uint32_t*>(&h0);
        u.y = *reinterpret_cast<uint32_t*>(&h1);
        dst[i] = u;
    }
}

// fp32 -> fp16 conversion: proj_w part (joined before GEMM2)
__global__ void convert_proj_kernel(const float4* __restrict__ pw) {
    const size_t N4 = (size_t)HID_DIM * OUT_DIM / 4;
    size_t stride = (size_t)gridDim.x * blockDim.x;
    uint2* dst = reinterpret_cast<uint2*>(g_pwh);
    for (size_t i = (size_t)blockIdx.x * blockDim.x + threadIdx.x; i < N4; i += stride) {
        float4 v = pw[i];
        __half2 h0 = __floats2half2_rn(v.x, v.y);
        __half2 h1 = __floats2half2_rn(v.z, v.w);
        uint2 u;
        u.x = *reinterpret_cast<uint32_t*>(&h0);
        u.y = *reinterpret_cast<uint32_t*>(&h1);
        dst[i] = u;
    }
}

// ---------------- fp16 mma.sync GEMM building blocks ----------------
constexpr int BM = 128, BN = 128, BK = 32, THREADS = 256, STAGES = 3;
constexpr int ASTRIDE = 80;                     // bytes/row: 32 halves + 8 pad
constexpr int BSTRIDE = 272;                    // bytes/row: 128 halves + 8 pad
constexpr int A_BYTES = BM * ASTRIDE;           // 10240
constexpr int B_BYTES = BK * BSTRIDE;           // 8704
constexpr int STAGE_BYTES = A_BYTES + B_BYTES;  // 18944
constexpr int PERM_OFF = STAGES * STAGE_BYTES;  // 56832
constexpr int GEMM_SMEM = PERM_OFF + BM * 4;    // 57344 (gemm1: +perm slice)
constexpr int GEMM2_SMEM = STAGES * STAGE_BYTES; // 56832
constexpr int MAX_T1 = 2304;                    // 72 m-tiles * 32 n-tiles upper bound

__device__ __forceinline__ void cp_async16(uint32_t sm, const void* g, bool p) {
    int bytes = p ? 16 : 0;
    asm volatile("cp.async.cg.shared.global [%0], [%1], 16, %2;\n"
                 :: "r"(sm), "l"(g), "r"(bytes));
}
__device__ __forceinline__ void cp_commit() { asm volatile("cp.async.commit_group;\n"); }
template <int N> __device__ __forceinline__ void cp_wait() {
    asm volatile("cp.async.wait_group %0;\n" :: "n"(N));
}
__device__ __forceinline__ void ldsm_x4(uint32_t* r, uint32_t addr) {
    asm volatile("ldmatrix.sync.aligned.m8n8.x4.shared.b16 {%0,%1,%2,%3}, [%4];\n"
                 : "=r"(r[0]), "=r"(r[1]), "=r"(r[2]), "=r"(r[3]) : "r"(addr));
}
__device__ __forceinline__ void ldsm_x4_t(uint32_t* r, uint32_t addr) {
    asm volatile("ldmatrix.sync.aligned.m8n8.x4.trans.shared.b16 {%0,%1,%2,%3}, [%4];\n"
                 : "=r"(r[0]), "=r"(r[1]), "=r"(r[2]), "=r"(r[3]) : "r"(addr));
}
__device__ __forceinline__ void mma_f16(float* c, const uint32_t* a,
                                        uint32_t b0, uint32_t b1) {
    asm volatile(
        "mma.sync.aligned.m16n8k16.row.col.f32.f16.f16.f32 "
        "{%0,%1,%2,%3}, {%4,%5,%6,%7}, {%8,%9}, {%0,%1,%2,%3};\n"
        : "+f"(c[0]), "+f"(c[1]), "+f"(c[2]), "+f"(c[3])
        : "r"(a[0]), "r"(a[1]), "r"(a[2]), "r"(a[3]), "r"(b0), "r"(b1));
}

// ---------------- GEMM1: expert GEMM, compact 1-D grid over real tiles ----------------
__global__ __launch_bounds__(THREADS, 2)
void gemm1_kernel(const float* __restrict__ biasGlob) {
    constexpr int KT = IN_DIM / BK;     // 32

    int t = blockIdx.x;
    if (t >= g_t1pref[N_EXP]) return;   // beyond real tile count
    int e = 0;
#pragma unroll
    for (int q = 1; q < N_EXP; q++)
        if (t >= g_t1pref[q]) e = q;
    int local = t - g_t1pref[e];
    int m_blk = (local >> 5) * BM;
    int n_blk = (local & 31) * BN;
    int M = g_counts2[e];

    extern __shared__ char smem[];
    uint32_t sm;
    asm("{ .reg .u64 t; cvta.to.shared.u64 t, %1; cvt.u32.u64 %0, t; }"
        : "=r"(sm) : "l"(smem));
    int* sperm = reinterpret_cast<int*>(smem + PERM_OFF);
    int tid = threadIdx.x;
    int lane = tid & 31, warp = tid >> 5;
    int wm = warp & 1, wn = warp >> 1;           // 2 warps (M=64) x 4 warps (N=32)
    uint32_t a_loff = (uint32_t)((lane & 15) * ASTRIDE + ((lane >> 4) & 1) * 16);
    uint32_t b_loff = (uint32_t)(((lane & 7) + ((lane >> 3) & 1) * 8) * BSTRIDE +
                                 ((lane >> 4) & 1) * 16);
    int g = lane >> 2, t4 = lane & 3;

    const __half* B = g_ewh + (size_t)e * IN_DIM * HID_DIM;
    const float* bias = biasGlob + (size_t)e * HID_DIM;
    __half* hC = g_hh + (size_t)g_offsets[e] * HID_DIM;

    if (tid < BM) {
        int gi = g_offsets[e] + m_blk + tid;
        sperm[tid] = g_perm[gi < BATCH ? gi : BATCH - 1];
    }
    __syncthreads();

    auto load_tiles = [&](int kt, int s) {
        uint32_t sa = sm + s * STAGE_BYTES;
#pragma unroll
        for (int n = 0; n < 2; n++) {          // A: 128 rows x 4 chunks
            int id = tid + n * THREADS;
            int r = id >> 2, c = id & 3;
            bool ok = (m_blk + r) < M;
            const __half* src = g_xh + (size_t)sperm[r] * IN_DIM + kt * BK + c * 8;
            cp_async16(sa + r * ASTRIDE + c * 16, src, ok);
        }
        uint32_t sb = sa + A_BYTES;
#pragma unroll
        for (int n = 0; n < 2; n++) {          // B: 32 rows x 16 chunks
            int id = tid + n * THREADS;
            int r = id >> 4, c = id & 15;
            const __half* src = B + (size_t)(kt * BK + r) * HID_DIM + n_blk + c * 8;
            cp_async16(sb + r * BSTRIDE + c * 16, src, true);
        }
        cp_commit();
    };

    float acc[4][4][4];
#pragma unroll
    for (int i = 0; i < 4; i++)
#pragma unroll
        for (int j = 0; j < 4; j++)
#pragma unroll
            for (int q = 0; q < 4; q++) acc[i][j][q] = 0.f;

    load_tiles(0, 0);
    load_tiles(1, 1);
    for (int kt = 0; kt < KT; kt++) {
        if (kt + 1 < KT) cp_wait<1>(); else cp_wait<0>();
        __syncthreads();
        if (kt + 2 < KT) load_tiles(kt + 2, (kt + 2) % STAGES);
        uint32_t sa = sm + (kt % STAGES) * STAGE_BYTES;
        uint32_t sb = sa + A_BYTES;
#pragma unroll
        for (int ks = 0; ks < 2; ks++) {
            uint32_t af[4][4], bf[2][4];
#pragma unroll
            for (int i = 0; i < 4; i++)
                ldsm_x4(af[i], sa + a_loff + (wm * 64 + i * 16) * ASTRIDE + ks * 32);
#pragma unroll
            for (int j = 0; j < 2; j++)
                ldsm_x4_t(bf[j], sb + b_loff + ks * 16 * BSTRIDE + (wn * 32 + j * 16) * 2);
#pragma unroll
            for (int i = 0; i < 4; i++) {
                mma_f16(acc[i][0], af[i], bf[0][0], bf[0][1]);
                mma_f16(acc[i][1], af[i], bf[0][2], bf[0][3]);
                mma_f16(acc[i][2], af[i], bf[1][0], bf[1][1]);
                mma_f16(acc[i][3], af[i], bf[1][2], bf[1][3]);
            }
        }
    }

    // epilogue -> g_hh (fp16)
#pragma unroll
    for (int i = 0; i < 4; i++) {
        int r0 = m_blk + wm * 64 + i * 16 + g;
        int r1 = r0 + 8;
#pragma unroll
        for (int j = 0; j < 4; j++) {
            int c = n_blk + wn * 32 + j * 8 + 2 * t4;
            float bv0 = bias[c], bv1 = bias[c + 1];
            if (r0 < M) {
                __half2 h = __floats2half2_rn(acc[i][j][0] + bv0, acc[i][j][1] + bv1);
                *reinterpret_cast<uint32_t*>(hC + (size_t)r0 * HID_DIM + c) =
                    *reinterpret_cast<uint32_t*>(&h);
            }
            if (r1 < M) {
                __half2 h = __floats2half2_rn(acc[i][j][2] + bv0, acc[i][j][3] + bv1);
                *reinterpret_cast<uint32_t*>(hC + (size_t)r1 * HID_DIM + c) =
                    *reinterpret_cast<uint32_t*>(&h);
            }
        }
    }
}

// ---------------- GEMM2: proj GEMM with split-K=4 ----------------
constexpr int KSPLIT = 4;
constexpr int KT2 = (HID_DIM / BK) / KSPLIT;   // 32 k-tiles per slice

__global__ __launch_bounds__(THREADS, 2)
void gemm2_kernel(const float* __restrict__ bias,
                  float* __restrict__ outGlob) {
    extern __shared__ char smem[];
    uint32_t sm;
    asm("{ .reg .u64 t; cvta.to.shared.u64 t, %1; cvt.u32.u64 %0, t; }"
        : "=r"(sm) : "l"(smem));
    int tid = threadIdx.x;
    int lane = tid & 31, warp = tid >> 5;
    int wm = warp & 1, wn = warp >> 1;           // 2 warps (M=64) x 4 warps (N=32)
    uint32_t a_loff = (uint32_t)((lane & 15) * ASTRIDE + ((lane >> 4) & 1) * 16);
    uint32_t b_loff = (uint32_t)(((lane & 7) + ((lane >> 3) & 1) * 8) * BSTRIDE +
                                 ((lane >> 4) & 1) * 16);
    int g = lane >> 2, t4 = lane & 3;

    int m_blk = blockIdx.y * BM;
    int n_blk = blockIdx.x * BN;
    int k0 = blockIdx.z * KT2;                   // k-tile base of this slice

    auto load_tiles = [&](int kt, int s) {
        uint32_t sa = sm + s * STAGE_BYTES;
#pragma unroll
        for (int n = 0; n < 2; n++) {          // A: 128 rows x 4 chunks
            int id = tid + n * THREADS;
            int r = id >> 2, c = id & 3;
            const __half* src = g_hh + (size_t)(m_blk + r) * HID_DIM
                                + (k0 + kt) * BK + c * 8;
            cp_async16(sa + r * ASTRIDE + c * 16, src, true);
        }
        uint32_t sb = sa + A_BYTES;
#pragma unroll
        for (int n = 0; n < 2; n++) {          // B: 32 rows x 16 chunks
            int id = tid + n * THREADS;
            int r = id >> 4, c = id & 15;
            const __half* src = g_pwh + (size_t)((k0 + kt) * BK + r) * OUT_DIM
                                + n_blk + c * 8;
            cp_async16(sb + r * BSTRIDE + c * 16, src, true);
        }
        cp_commit();
    };

    float acc[4][4][4];
#pragma unroll
    for (int i = 0; i < 4; i++)
#pragma unroll
        for (int j = 0; j < 4; j++)
#pragma unroll
            for (int q = 0; q < 4; q++) acc[i][j][q] = 0.f;

    load_tiles(0, 0);
    load_tiles(1, 1);
    for (int kt = 0; kt < KT2; kt++) {
        if (kt + 1 < KT2) cp_wait<1>(); else cp_wait<0>();
        __syncthreads();
        if (kt + 2 < KT2) load_tiles(kt + 2, (kt + 2) % STAGES);
        uint32_t sa = sm + (kt % STAGES) * STAGE_BYTES;
        uint32_t sb = sa + A_BYTES;
#pragma unroll
        for (int ks = 0; ks < 2; ks++) {
            uint32_t af[4][4], bf[2][4];
#pragma unroll
            for (int i = 0; i < 4; i++)
                ldsm_x4(af[i], sa + a_loff + (wm * 64 + i * 16) * ASTRIDE + ks * 32);
#pragma unroll
            for (int j = 0; j < 2; j++)
                ldsm_x4_t(bf[j], sb + b_loff + ks * 16 * BSTRIDE + (wn * 32 + j * 16) * 2);
#pragma unroll
            for (int i = 0; i < 4; i++) {
                mma_f16(acc[i][0], af[i], bf[0][0], bf[0][1]);
                mma_f16(acc[i][1], af[i], bf[0][2], bf[0][3]);
                mma_f16(acc[i][2], af[i], bf[1][0], bf[1][1]);
                mma_f16(acc[i][3], af[i], bf[1][2], bf[1][3]);
            }
        }
    }

    // epilogue: accumulate partial into d_out (scattered rows), bias on slice 0
    bool addBias = (blockIdx.z == 0);
#pragma unroll
    for (int i = 0; i < 4; i++) {
        int r0 = m_blk + wm * 64 + i * 16 + g;
        int r1 = r0 + 8;
        int o0 = g_perm[r0], o1 = g_perm[r1];
        float* p0r = outGlob + (size_t)o0 * OUT_DIM;
        float* p1r = outGlob + (size_t)o1 * OUT_DIM;
#pragma unroll
        for (int j = 0; j < 4; j++) {
            int c = n_blk + wn * 32 + j * 8 + 2 * t4;
            float bv0 = addBias ? bias[c] : 0.f;
            float bv1 = addBias ? bias[c + 1] : 0.f;
            atomicAdd(p0r + c,     acc[i][j][0] + bv0);
            atomicAdd(p0r + c + 1, acc[i][j][1] + bv1);
            atomicAdd(p1r + c,     acc[i][j][2] + bv0);
            atomicAdd(p1r + c + 1, acc[i][j][3] + bv1);
        }
    }
}

// ---------------- launch ----------------
extern "C" void kernel_launch(void* const* d_in, const int* in_sizes, int n_in,
                              void* d_out, int out_size) {
    const float* x        = (const float*)d_in[0];
    const float* router_w = (const float*)d_in[1];
    const float* router_b = (const float*)d_in[2];
    const float* expert_w = (const float*)d_in[3];
    const float* expert_b = (const float*)d_in[4];
    const float* proj_w   = (const float*)d_in[5];
    const float* proj_b   = (const float*)d_in[6];

    float* out       = (float*)d_out;
    float* route_out = out + (size_t)BATCH * OUT_DIM;   // [out | one_hot]

    // one-time setup on the FIRST (uncaptured correctness) call; reused during capture
    static cudaStream_t s2 = nullptr;
    static cudaEvent_t ev_fork = nullptr, ev_j1 = nullptr, ev_j2 = nullptr;
    if (!s2) {
        cudaStreamCreateWithFlags(&s2, cudaStreamNonBlocking);
        cudaEventCreateWithFlags(&ev_fork, cudaEventDisableTiming);
        cudaEventCreateWithFlags(&ev_j1, cudaEventDisableTiming);
        cudaEventCreateWithFlags(&ev_j2, cudaEventDisableTiming);
        cudaFuncSetAttribute(gemm1_kernel,
                             cudaFuncAttributeMaxDynamicSharedMemorySize, GEMM_SMEM);
        cudaFuncSetAttribute(gemm2_kernel,
                             cudaFuncAttributeMaxDynamicSharedMemorySize, GEMM2_SMEM);
    }

    // fork: side stream does weight conversion + out zeroing, overlapping
    // with router/perm on the main stream.
    cudaEventRecord(ev_fork, 0);
    cudaStreamWaitEvent(s2, ev_fork, 0);
    convert_expert_kernel<<<2048, 256, 0, s2>>>((const float4*)expert_w);
    cudaEventRecord(ev_j1, s2);                      // expert weights ready
    convert_proj_kernel<<<256, 256, 0, s2>>>((const float4*)proj_w);
    zero_out_kernel<<<512, 256, 0, s2>>>((float4*)out);
    cudaEventRecord(ev_j2, s2);                      // proj weights + zeroed out ready

    router_kernel<<<BATCH / (TPW * 4), 128>>>(x, router_w, router_b, route_out);
    perm_kernel<<<BATCH / 256, 256>>>();

    cudaStreamWaitEvent(0, ev_j1, 0);
    gemm1_kernel<<<MAX_T1, THREADS, GEMM_SMEM>>>(expert_b);

    cudaStreamWaitEvent(0, ev_j2, 0);
    gemm2_kernel<<<dim3(OUT_DIM / BN, BATCH / BM, KSPLIT),
                   THREADS, GEMM2_SMEM>>>(proj_b, out);
}